// round 2
// baseline (speedup 1.0000x reference)
#include <cuda_runtime.h>
#include <math.h>

#define P_   1024
#define L_   32
#define E_   512
#define D_   768
#define NL_  6
#define FF_  3072
#define HPA_ 4
#define HTR_ 8

// ---------------- scratch (device globals; no allocation allowed) ----------------
__device__ float g_emb[P_ * L_ * E_];        // 67 MB: embeddings, later reused as local attn output
__device__ float g_qkv[P_ * L_ * 3 * E_];    // 201 MB: local qkv; reused for transformer qkv (1024x2304)
__device__ float g_ctx[P_ * L_ * E_];        // 67 MB: local attn context; reused for transformer ctx (1024x768)
__device__ float g_pr [P_ * E_];             // patch_repr
__device__ float g_h  [P_ * D_];             // hidden
__device__ float g_hn [P_ * D_];             // layernorm output
__device__ float g_ff [P_ * FF_];            // FFN intermediate

// ---------------- helpers ----------------
__device__ __forceinline__ float gelu_exact(float x) {
    return 0.5f * x * (1.0f + erff(x * 0.70710678118654752440f));
}

// ---------------- embedding + mask ----------------
__global__ void embed_kernel(const int* __restrict__ tokens, const int* __restrict__ lengths,
                             const float* __restrict__ byte_emb, const float* __restrict__ lpos,
                             float* __restrict__ out) {
    int pl = blockIdx.x;            // 0..P*L-1
    int p  = pl >> 5;
    int l  = pl & 31;
    int t  = threadIdx.x;           // 256
    bool valid = (l < lengths[p]);
    int tok = tokens[pl];
    const float* be = byte_emb + (size_t)tok * E_;
    const float* lp = lpos + (size_t)l * E_;
    float* o = out + (size_t)pl * E_;
    #pragma unroll
    for (int e = t; e < E_; e += 256)
        o[e] = valid ? (be[e] + lp[e]) : 0.0f;
}

// ---------------- SGEMM: C[M,N] = epilogue(A[M,K] @ W[N,K]^T + bias) (+Res) ----------------
// ACT: 0 = none, 1 = exact GELU (applied before residual add)
template<int ACT>
__global__ void __launch_bounds__(256)
sgemm_kernel(const float* __restrict__ A, const float* __restrict__ W,
             const float* __restrict__ bias, const float* __restrict__ Res,
             float* __restrict__ C, int M, int N, int K) {
    __shared__ __align__(16) float As[16][68];   // [k][m], padded, 16B-aligned rows (68*4=272=17*16)
    __shared__ __align__(16) float Bs[16][68];   // [k][n]

    int tid = threadIdx.x;
    int tx = tid & 15;          // 0..15 -> n
    int ty = tid >> 4;          // 0..15 -> m
    int m0 = blockIdx.y * 64;
    int n0 = blockIdx.x * 64;

    float acc[4][4];
    #pragma unroll
    for (int i = 0; i < 4; i++)
        #pragma unroll
        for (int j = 0; j < 4; j++) acc[i][j] = 0.0f;

    int lc = tid & 15;          // k offset within tile
    int lr0 = tid >> 4;         // row start

    for (int k0 = 0; k0 < K; k0 += 16) {
        #pragma unroll
        for (int w = 0; w < 4; w++) {
            int r = lr0 + w * 16;
            As[lc][r] = A[(size_t)(m0 + r) * K + k0 + lc];
            Bs[lc][r] = W[(size_t)(n0 + r) * K + k0 + lc];
        }
        __syncthreads();
        #pragma unroll
        for (int kk = 0; kk < 16; kk++) {
            float4 av = *reinterpret_cast<const float4*>(&As[kk][ty * 4]);
            float4 bv = *reinterpret_cast<const float4*>(&Bs[kk][tx * 4]);
            float a[4] = {av.x, av.y, av.z, av.w};
            float b[4] = {bv.x, bv.y, bv.z, bv.w};
            #pragma unroll
            for (int i = 0; i < 4; i++)
                #pragma unroll
                for (int j = 0; j < 4; j++)
                    acc[i][j] = fmaf(a[i], b[j], acc[i][j]);
        }
        __syncthreads();
    }

    #pragma unroll
    for (int i = 0; i < 4; i++) {
        int m = m0 + ty * 4 + i;
        #pragma unroll
        for (int j = 0; j < 4; j++) {
            int n = n0 + tx * 4 + j;
            float v = acc[i][j];
            if (bias) v += bias[n];
            if (ACT == 1) v = gelu_exact(v);
            if (Res) v += Res[(size_t)m * N + n];
            C[(size_t)m * N + n] = v;
        }
    }
}

// ---------------- local (per-patch) attention: S=32, d=128, 4 heads ----------------
// grid (P, HPA), 128 threads. qkv layout: [P*L, 1536] with q|k|v blocks of 512.
__global__ void __launch_bounds__(128)
local_attn_kernel(const float* __restrict__ qkv, const int* __restrict__ lengths,
                  float* __restrict__ ctx) {
    __shared__ float bufA[32][129];   // q, then reused for v
    __shared__ float bufK[32][129];
    __shared__ float s[32][33];

    int p = blockIdx.x, h = blockIdx.y, t = threadIdx.x;
    int len = lengths[p];
    const float scale = 0.08838834764831845f;   // 1/sqrt(128)
    const float* base = qkv + (size_t)p * 32 * 1536 + h * 128;

    #pragma unroll 4
    for (int l = 0; l < 32; l++) {
        bufA[l][t] = base[(size_t)l * 1536 + t] * scale;   // q (scaled)
        bufK[l][t] = base[(size_t)l * 1536 + 512 + t];     // k
    }
    __syncthreads();

    // scores: 1024 pairs, 8 per thread
    #pragma unroll
    for (int w = 0; w < 8; w++) {
        int idx = t + w * 128;
        int i = idx >> 5, j = idx & 31;
        float acc = 0.0f;
        #pragma unroll 8
        for (int kk = 0; kk < 128; kk++) acc = fmaf(bufA[i][kk], bufK[j][kk], acc);
        s[i][j] = (j < len) ? acc : -1e30f;
    }
    __syncthreads();

    // softmax per row (thread t < 32 owns row t)
    if (t < 32) {
        float mx = -1e30f;
        #pragma unroll
        for (int j = 0; j < 32; j++) mx = fmaxf(mx, s[t][j]);
        float sum = 0.0f;
        #pragma unroll
        for (int j = 0; j < 32; j++) { float e = __expf(s[t][j] - mx); s[t][j] = e; sum += e; }
        float inv = 1.0f / sum;
        #pragma unroll
        for (int j = 0; j < 32; j++) s[t][j] *= inv;
    }
    __syncthreads();

    // reload bufA with v
    #pragma unroll 4
    for (int l = 0; l < 32; l++)
        bufA[l][t] = base[(size_t)l * 1536 + 1024 + t];
    __syncthreads();

    // ctx[l][t] = sum_j s[l][j] * v[j][t]
    for (int l = 0; l < 32; l++) {
        float acc = 0.0f;
        #pragma unroll
        for (int j = 0; j < 32; j++) acc = fmaf(s[l][j], bufA[j][t], acc);
        ctx[(size_t)(p * 32 + l) * 512 + h * 128 + t] = acc;
    }
}

// ---------------- masked mean over valid bytes ----------------
__global__ void meanpool_kernel(const float* __restrict__ attn_out, const int* __restrict__ lengths,
                                float* __restrict__ pr) {
    int p = blockIdx.x, t = threadIdx.x;   // 512 threads
    int len = lengths[p];
    const float* b = attn_out + (size_t)p * 32 * 512 + t;
    float acc = 0.0f;
    for (int l = 0; l < len; l++) acc += b[(size_t)l * 512];
    pr[(size_t)p * 512 + t] = acc / (float)len;
}

// ---------------- layernorm over D=768 (256 threads x 3 elems) ----------------
__global__ void ln_kernel(const float* __restrict__ x, const float* __restrict__ w,
                          const float* __restrict__ b, float* __restrict__ y) {
    __shared__ float red[8];
    int m = blockIdx.x, t = threadIdx.x;
    const float* xr = x + (size_t)m * D_;
    float v0 = xr[t], v1 = xr[t + 256], v2 = xr[t + 512];

    // sum
    float s = v0 + v1 + v2;
    #pragma unroll
    for (int o = 16; o; o >>= 1) s += __shfl_xor_sync(0xffffffffu, s, o);
    if ((t & 31) == 0) red[t >> 5] = s;
    __syncthreads();
    if (t < 8) {
        float v = red[t];
        #pragma unroll
        for (int o = 4; o; o >>= 1) v += __shfl_xor_sync(0xffu, v, o);
        if (t == 0) red[0] = v;
    }
    __syncthreads();
    float mu = red[0] * (1.0f / D_);
    __syncthreads();

    float d0 = v0 - mu, d1 = v1 - mu, d2 = v2 - mu;
    float sq = d0 * d0 + d1 * d1 + d2 * d2;
    #pragma unroll
    for (int o = 16; o; o >>= 1) sq += __shfl_xor_sync(0xffffffffu, sq, o);
    if ((t & 31) == 0) red[t >> 5] = sq;
    __syncthreads();
    if (t < 8) {
        float v = red[t];
        #pragma unroll
        for (int o = 4; o; o >>= 1) v += __shfl_xor_sync(0xffu, v, o);
        if (t == 0) red[0] = v;
    }
    __syncthreads();
    float rstd = rsqrtf(red[0] * (1.0f / D_) + 1e-5f);

    float* yr = y + (size_t)m * D_;
    yr[t]       = d0 * rstd * w[t]       + b[t];
    yr[t + 256] = d1 * rstd * w[t + 256] + b[t + 256];
    yr[t + 512] = d2 * rstd * w[t + 512] + b[t + 512];
}

// ---------------- transformer attention: S=1024, d=96, 8 heads ----------------
// grid (128 q-tiles of 8 rows, 8 heads), 128 threads.
// qkv layout: [1024, 2304] with q|k|v blocks of 768; head h = cols [h*96, h*96+96).
__global__ void __launch_bounds__(128)
trans_attn_kernel(const float* __restrict__ qkv, float* __restrict__ ctx) {
    __shared__ float sQ[8][96];
    __shared__ float sKV[32][97];
    __shared__ float sS[8][1024];

    int qt = blockIdx.x, h = blockIdx.y, t = threadIdx.x;
    int q0 = qt * 8;
    const float scale = 0.10206207261596575f;   // 1/sqrt(96)

    for (int u = t; u < 8 * 96; u += 128) {
        int i = u / 96, dd = u - i * 96;
        sQ[i][dd] = qkv[(size_t)(q0 + i) * 2304 + h * 96 + dd] * scale;
    }
    __syncthreads();

    // scores
    for (int kt = 0; kt < 32; kt++) {
        int j0 = kt * 32;
        for (int u = t; u < 32 * 96; u += 128) {
            int j = u / 96, dd = u - j * 96;
            sKV[j][dd] = qkv[(size_t)(j0 + j) * 2304 + 768 + h * 96 + dd];
        }
        __syncthreads();
        #pragma unroll
        for (int w = 0; w < 2; w++) {
            int idx = t + w * 128;
            int i = idx >> 5, j = idx & 31;
            float acc = 0.0f;
            #pragma unroll 8
            for (int kk = 0; kk < 96; kk++) acc = fmaf(sQ[i][kk], sKV[j][kk], acc);
            sS[i][j0 + j] = acc;
        }
        __syncthreads();
    }

    // softmax: 16 threads per row
    {
        int i = t >> 4, lane = t & 15;
        float mx = -1e30f;
        for (int j = lane; j < 1024; j += 16) mx = fmaxf(mx, sS[i][j]);
        #pragma unroll
        for (int o = 8; o; o >>= 1) mx = fmaxf(mx, __shfl_xor_sync(0xffffffffu, mx, o, 16));
        float sum = 0.0f;
        for (int j = lane; j < 1024; j += 16) { float e = __expf(sS[i][j] - mx); sS[i][j] = e; sum += e; }
        #pragma unroll
        for (int o = 8; o; o >>= 1) sum += __shfl_xor_sync(0xffffffffu, sum, o, 16);
        float inv = 1.0f / sum;
        for (int j = lane; j < 1024; j += 16) sS[i][j] *= inv;
    }
    __syncthreads();

    // ctx = softmax @ V : 768 outputs, 6 per thread
    float acc[6] = {0, 0, 0, 0, 0, 0};
    int io[6], ddo[6];
    #pragma unroll
    for (int w = 0; w < 6; w++) { int o = t + w * 128; io[w] = o / 96; ddo[w] = o - io[w] * 96; }

    for (int vt = 0; vt < 32; vt++) {
        int j0 = vt * 32;
        for (int u = t; u < 32 * 96; u += 128) {
            int j = u / 96, dd = u - j * 96;
            sKV[j][dd] = qkv[(size_t)(j0 + j) * 2304 + 1536 + h * 96 + dd];
        }
        __syncthreads();
        #pragma unroll
        for (int w = 0; w < 6; w++) {
            float a = 0.0f;
            #pragma unroll
            for (int j = 0; j < 32; j++) a = fmaf(sS[io[w]][j0 + j], sKV[j][ddo[w]], a);
            acc[w] += a;
        }
        __syncthreads();
    }
    #pragma unroll
    for (int w = 0; w < 6; w++)
        ctx[(size_t)(q0 + io[w]) * 768 + h * 96 + ddo[w]] = acc[w];
}

// ---------------- host driver ----------------
static void run_gemm(const float* A, const float* W, const float* bias, const float* Res,
                     float* C, int M, int N, int K, int act) {
    dim3 grid(N / 64, M / 64), block(256);
    if (act) sgemm_kernel<1><<<grid, block>>>(A, W, bias, Res, C, M, N, K);
    else     sgemm_kernel<0><<<grid, block>>>(A, W, bias, Res, C, M, N, K);
}

extern "C" void kernel_launch(void* const* d_in, const int* in_sizes, int n_in,
                              void* d_out, int out_size) {
    const int*   tokens   = (const int*)d_in[0];
    const int*   lengths  = (const int*)d_in[1];
    const float* byte_emb = (const float*)d_in[2];
    const float* lpos     = (const float*)d_in[3];
    const float* ppos     = (const float*)d_in[4];
    const float* pa_qkv_w = (const float*)d_in[5];
    const float* pa_qkv_b = (const float*)d_in[6];
    const float* pa_out_w = (const float*)d_in[7];
    const float* pa_out_b = (const float*)d_in[8];
    const float* proj_w   = (const float*)d_in[9];
    const float* proj_b   = (const float*)d_in[10];
    const float* lqkv_w   = (const float*)d_in[11];
    const float* lqkv_b   = (const float*)d_in[12];
    const float* lout_w   = (const float*)d_in[13];
    const float* lout_b   = (const float*)d_in[14];
    const float* ln1w     = (const float*)d_in[15];
    const float* ln1b     = (const float*)d_in[16];
    const float* ln2w     = (const float*)d_in[17];
    const float* ln2b     = (const float*)d_in[18];
    const float* ff1w     = (const float*)d_in[19];
    const float* ff1b     = (const float*)d_in[20];
    const float* ff2w     = (const float*)d_in[21];
    const float* ff2b     = (const float*)d_in[22];
    const float* lnfw     = (const float*)d_in[23];
    const float* lnfb     = (const float*)d_in[24];
    float* out = (float*)d_out;

    float *emb, *qkvb, *ctxb, *pr, *h, *hn, *ffb;
    cudaGetSymbolAddress((void**)&emb,  g_emb);
    cudaGetSymbolAddress((void**)&qkvb, g_qkv);
    cudaGetSymbolAddress((void**)&ctxb, g_ctx);
    cudaGetSymbolAddress((void**)&pr,   g_pr);
    cudaGetSymbolAddress((void**)&h,    g_h);
    cudaGetSymbolAddress((void**)&hn,   g_hn);
    cudaGetSymbolAddress((void**)&ffb,  g_ff);

    // 1) embeddings (masked)
    embed_kernel<<<P_ * L_, 256>>>(tokens, lengths, byte_emb, lpos, emb);

    // 2) local qkv: [32768,512] @ [1536,512]^T
    run_gemm(emb, pa_qkv_w, pa_qkv_b, nullptr, qkvb, P_ * L_, 3 * E_, E_, 0);

    // 3) per-patch attention
    local_attn_kernel<<<dim3(P_, HPA_), 128>>>(qkvb, lengths, ctxb);

    // 4) local out-proj -> reuse emb as attn output
    run_gemm(ctxb, pa_out_w, pa_out_b, nullptr, emb, P_ * L_, E_, E_, 0);

    // 5) masked mean -> patch_repr
    meanpool_kernel<<<P_, 512>>>(emb, lengths, pr);

    // 6) project + patch positions -> h
    run_gemm(pr, proj_w, proj_b, ppos, h, P_, D_, E_, 0);

    // 7) transformer layers
    for (int i = 0; i < NL_; i++) {
        ln_kernel<<<P_, 256>>>(h, ln1w + (size_t)i * D_, ln1b + (size_t)i * D_, hn);
        run_gemm(hn, lqkv_w + (size_t)i * 3 * D_ * D_, lqkv_b + (size_t)i * 3 * D_,
                 nullptr, qkvb, P_, 3 * D_, D_, 0);
        trans_attn_kernel<<<dim3(128, HTR_), 128>>>(qkvb, ctxb);
        run_gemm(ctxb, lout_w + (size_t)i * D_ * D_, lout_b + (size_t)i * D_,
                 h, h, P_, D_, D_, 0);
        ln_kernel<<<P_, 256>>>(h, ln2w + (size_t)i * D_, ln2b + (size_t)i * D_, hn);
        run_gemm(hn, ff1w + (size_t)i * FF_ * D_, ff1b + (size_t)i * FF_,
                 nullptr, ffb, P_, FF_, D_, 1);
        run_gemm(ffb, ff2w + (size_t)i * D_ * FF_, ff2b + (size_t)i * D_,
                 h, h, P_, D_, FF_, 0);
    }

    // 8) final layernorm -> output
    ln_kernel<<<P_, 256>>>(h, lnfw, lnfb, out);
}

// round 8
// speedup vs baseline: 1.5559x; 1.5559x over previous
#include <cuda_runtime.h>
#include <cuda_bf16.h>
#include <cstdint>
#include <math.h>

#define P_   1024
#define L_   32
#define E_   512
#define D_   768
#define NL_  6
#define FF_  3072
#define HPA_ 4
#define HTR_ 8

// ---------------- scratch (device globals; no allocation allowed) ----------------
__device__ float g_emb[P_ * L_ * E_];
__device__ float g_qkv[P_ * L_ * 3 * E_];
__device__ float g_ctx[P_ * L_ * E_];
__device__ float g_pr [P_ * E_];
__device__ float g_h  [P_ * D_];
__device__ float g_hn [P_ * D_];
__device__ float g_ff [P_ * FF_];
// bf16 hi/lo split buffers (max A = 32768x512, max W = 3072x768)
__device__ __nv_bfloat16 g_ahi[P_ * L_ * E_];
__device__ __nv_bfloat16 g_alo[P_ * L_ * E_];
__device__ __nv_bfloat16 g_whi[FF_ * D_];
__device__ __nv_bfloat16 g_wlo[FF_ * D_];

// ---------------- helpers ----------------
__device__ __forceinline__ float gelu_exact(float x) {
    return 0.5f * x * (1.0f + erff(x * 0.70710678118654752440f));
}
__device__ __forceinline__ uint32_t smem_u32(const void* p) {
    uint32_t a;
    asm("{ .reg .u64 t; cvta.to.shared.u64 t, %1; cvt.u32.u64 %0, t; }" : "=r"(a) : "l"(p));
    return a;
}
__device__ __forceinline__ void cp16(uint32_t dst, const void* src) {
    asm volatile("cp.async.cg.shared.global [%0], [%1], 16;" :: "r"(dst), "l"(src));
}
__device__ __forceinline__ void cp_commit() {
    asm volatile("cp.async.commit_group;" ::: "memory");
}
__device__ __forceinline__ void ldsm4(uint32_t& r0, uint32_t& r1, uint32_t& r2, uint32_t& r3,
                                      uint32_t addr) {
    asm volatile("ldmatrix.sync.aligned.m8n8.x4.shared.b16 {%0,%1,%2,%3}, [%4];"
                 : "=r"(r0), "=r"(r1), "=r"(r2), "=r"(r3) : "r"(addr));
}
__device__ __forceinline__ void mma_bf16(float* c, const uint32_t* a, const uint32_t* b) {
    asm volatile(
        "mma.sync.aligned.m16n8k16.row.col.f32.bf16.bf16.f32 "
        "{%0,%1,%2,%3}, {%4,%5,%6,%7}, {%8,%9}, {%0,%1,%2,%3};"
        : "+f"(c[0]), "+f"(c[1]), "+f"(c[2]), "+f"(c[3])
        : "r"(a[0]), "r"(a[1]), "r"(a[2]), "r"(a[3]), "r"(b[0]), "r"(b[1]));
}

// ---------------- fp32 -> bf16 hi/lo split ----------------
__global__ void split_kernel(const float* __restrict__ x, __nv_bfloat16* __restrict__ hi,
                             __nv_bfloat16* __restrict__ lo, int n4) {
    int i = blockIdx.x * 256 + threadIdx.x;
    if (i >= n4) return;
    float4 v = reinterpret_cast<const float4*>(x)[i];
    __nv_bfloat16 h0 = __float2bfloat16(v.x), h1 = __float2bfloat16(v.y);
    __nv_bfloat16 h2 = __float2bfloat16(v.z), h3 = __float2bfloat16(v.w);
    __nv_bfloat162* hp = reinterpret_cast<__nv_bfloat162*>(hi);
    __nv_bfloat162* lp = reinterpret_cast<__nv_bfloat162*>(lo);
    hp[2 * i]     = __nv_bfloat162(h0, h1);
    hp[2 * i + 1] = __nv_bfloat162(h2, h3);
    lp[2 * i]     = __nv_bfloat162(__float2bfloat16(v.x - __bfloat162float(h0)),
                                   __float2bfloat16(v.y - __bfloat162float(h1)));
    lp[2 * i + 1] = __nv_bfloat162(__float2bfloat16(v.z - __bfloat162float(h2)),
                                   __float2bfloat16(v.w - __bfloat162float(h3)));
}

// ---------------- HMMA GEMM: C[M,N] = epi(A@W^T + bias) (+Res) ----------------
// bf16 hi/lo operands, fp32 accum. BM=BN=128, BK=32, 256 threads (4x2 warps).
// smem per stage: 4 tiles (Ahi,Alo,Bhi,Blo), each 128 rows x 40 bf16 (80B stride).
#define TPAD    40
#define TILE_B  (128 * TPAD * 2)     // 10240
#define STAGE_B (4 * TILE_B)         // 40960
#define GSMEM   (2 * STAGE_B)        // 81920

template<int ACT>
__global__ void __launch_bounds__(256, 1)
mma_gemm(const __nv_bfloat16* __restrict__ Ahi, const __nv_bfloat16* __restrict__ Alo,
         const __nv_bfloat16* __restrict__ Whi, const __nv_bfloat16* __restrict__ Wlo,
         const float* __restrict__ bias, const float* __restrict__ Res,
         float* __restrict__ C, int M, int N, int K) {
    extern __shared__ char smem[];
    uint32_t sb = smem_u32(smem);
    int tid = threadIdx.x, lane = tid & 31, warp = tid >> 5;
    int wm = warp >> 1, wn = warp & 1;              // 4 x 2 warp grid
    int m0 = blockIdx.y * 128, n0 = blockIdx.x * 128;

    float acc[2][8][4];
    #pragma unroll
    for (int mf = 0; mf < 2; mf++)
        #pragma unroll
        for (int nf = 0; nf < 8; nf++)
            #pragma unroll
            for (int q = 0; q < 4; q++) acc[mf][nf][q] = 0.0f;

    auto load_stage = [&](int s, int k0) {
        uint32_t base = sb + s * STAGE_B;
        #pragma unroll
        for (int i = 0; i < 2; i++) {
            int chunk = tid + i * 256;              // 512 chunks per tile
            int r = chunk >> 2, c = chunk & 3;
            uint32_t doff = (uint32_t)(r * 80 + c * 16);
            size_t aoff = (size_t)(m0 + r) * K + k0 + c * 8;
            size_t boff = (size_t)(n0 + r) * K + k0 + c * 8;
            cp16(base + doff,              Ahi + aoff);
            cp16(base + TILE_B + doff,     Alo + aoff);
            cp16(base + 2 * TILE_B + doff, Whi + boff);
            cp16(base + 3 * TILE_B + doff, Wlo + boff);
        }
        cp_commit();
    };

    auto compute_stage = [&](int s) {
        uint32_t base = sb + s * STAGE_B;
        #pragma unroll
        for (int ks = 0; ks < 2; ks++) {
            int kk = ks * 16;
            uint32_t ahi[2][4], alo[2][4];
            #pragma unroll
            for (int mf = 0; mf < 2; mf++) {
                int row = wm * 32 + mf * 16 + (lane & 15);
                int kc  = kk + ((lane >> 4) << 3);
                uint32_t off = (uint32_t)(row * 80 + kc * 2);
                ldsm4(ahi[mf][0], ahi[mf][1], ahi[mf][2], ahi[mf][3], base + off);
                ldsm4(alo[mf][0], alo[mf][1], alo[mf][2], alo[mf][3], base + TILE_B + off);
            }
            uint32_t bhi[8][2], blo[8][2];
            #pragma unroll
            for (int nq = 0; nq < 4; nq++) {
                int row = wn * 64 + nq * 16 + ((lane >> 4) << 3) + (lane & 7);
                int kc  = kk + (((lane >> 3) & 1) << 3);
                uint32_t off = (uint32_t)(row * 80 + kc * 2);
                uint32_t r0, r1, r2, r3;
                ldsm4(r0, r1, r2, r3, base + 2 * TILE_B + off);
                bhi[2 * nq][0] = r0; bhi[2 * nq][1] = r1;
                bhi[2 * nq + 1][0] = r2; bhi[2 * nq + 1][1] = r3;
                ldsm4(r0, r1, r2, r3, base + 3 * TILE_B + off);
                blo[2 * nq][0] = r0; blo[2 * nq][1] = r1;
                blo[2 * nq + 1][0] = r2; blo[2 * nq + 1][1] = r3;
            }
            #pragma unroll
            for (int mf = 0; mf < 2; mf++)
                #pragma unroll
                for (int nf = 0; nf < 8; nf++) {
                    mma_bf16(acc[mf][nf], ahi[mf], bhi[nf]);
                    mma_bf16(acc[mf][nf], ahi[mf], blo[nf]);
                    mma_bf16(acc[mf][nf], alo[mf], bhi[nf]);
                }
        }
    };

    int nk = K >> 5;
    load_stage(0, 0);
    for (int kt = 0; kt < nk; kt++) {
        if (kt + 1 < nk) {
            load_stage((kt + 1) & 1, (kt + 1) << 5);
            asm volatile("cp.async.wait_group 1;" ::: "memory");
        } else {
            asm volatile("cp.async.wait_group 0;" ::: "memory");
        }
        __syncthreads();
        compute_stage(kt & 1);
        __syncthreads();
    }

    // epilogue: fragment (mf,nf): rows m0+wm*32+mf*16+{lane/4, +8}, cols n0+wn*64+nf*8+(lane%4)*2
    #pragma unroll
    for (int mf = 0; mf < 2; mf++) {
        int rbase = m0 + wm * 32 + mf * 16 + (lane >> 2);
        #pragma unroll
        for (int nf = 0; nf < 8; nf++) {
            int cbase = n0 + wn * 64 + nf * 8 + (lane & 3) * 2;
            #pragma unroll
            for (int half = 0; half < 2; half++) {
                int m = rbase + half * 8;
                float2 v;
                v.x = acc[mf][nf][half * 2];
                v.y = acc[mf][nf][half * 2 + 1];
                if (bias) { v.x += bias[cbase]; v.y += bias[cbase + 1]; }
                if (ACT == 1) { v.x = gelu_exact(v.x); v.y = gelu_exact(v.y); }
                if (Res) {
                    const float2 rv = *reinterpret_cast<const float2*>(Res + (size_t)m * N + cbase);
                    v.x += rv.x; v.y += rv.y;
                }
                *reinterpret_cast<float2*>(C + (size_t)m * N + cbase) = v;
            }
        }
    }
}

// ---------------- embedding + mask ----------------
__global__ void embed_kernel(const int* __restrict__ tokens, const int* __restrict__ lengths,
                             const float* __restrict__ byte_emb, const float* __restrict__ lpos,
                             float* __restrict__ out) {
    int pl = blockIdx.x;
    int p  = pl >> 5;
    int l  = pl & 31;
    int t  = threadIdx.x;
    bool valid = (l < lengths[p]);
    int tok = tokens[pl];
    const float* be = byte_emb + (size_t)tok * E_;
    const float* lp = lpos + (size_t)l * E_;
    float* o = out + (size_t)pl * E_;
    #pragma unroll
    for (int e = t; e < E_; e += 256)
        o[e] = valid ? (be[e] + lp[e]) : 0.0f;
}

// ---------------- local (per-patch) attention: S=32, d=128, 4 heads ----------------
__global__ void __launch_bounds__(128)
local_attn_kernel(const float* __restrict__ qkv, const int* __restrict__ lengths,
                  float* __restrict__ ctx) {
    __shared__ float bufA[32][129];
    __shared__ float bufK[32][129];
    __shared__ float s[32][33];

    int p = blockIdx.x, h = blockIdx.y, t = threadIdx.x;
    int len = lengths[p];
    const float scale = 0.08838834764831845f;
    const float* base = qkv + (size_t)p * 32 * 1536 + h * 128;

    #pragma unroll 4
    for (int l = 0; l < 32; l++) {
        bufA[l][t] = base[(size_t)l * 1536 + t] * scale;
        bufK[l][t] = base[(size_t)l * 1536 + 512 + t];
    }
    __syncthreads();

    #pragma unroll
    for (int w = 0; w < 8; w++) {
        int idx = t + w * 128;
        int i = idx >> 5, j = idx & 31;
        float acc = 0.0f;
        #pragma unroll 8
        for (int kk = 0; kk < 128; kk++) acc = fmaf(bufA[i][kk], bufK[j][kk], acc);
        s[i][j] = (j < len) ? acc : -1e30f;
    }
    __syncthreads();

    if (t < 32) {
        float mx = -1e30f;
        #pragma unroll
        for (int j = 0; j < 32; j++) mx = fmaxf(mx, s[t][j]);
        float sum = 0.0f;
        #pragma unroll
        for (int j = 0; j < 32; j++) { float e = __expf(s[t][j] - mx); s[t][j] = e; sum += e; }
        float inv = 1.0f / sum;
        #pragma unroll
        for (int j = 0; j < 32; j++) s[t][j] *= inv;
    }
    __syncthreads();

    #pragma unroll 4
    for (int l = 0; l < 32; l++)
        bufA[l][t] = base[(size_t)l * 1536 + 1024 + t];
    __syncthreads();

    for (int l = 0; l < 32; l++) {
        float acc = 0.0f;
        #pragma unroll
        for (int j = 0; j < 32; j++) acc = fmaf(s[l][j], bufA[j][t], acc);
        ctx[(size_t)(p * 32 + l) * 512 + h * 128 + t] = acc;
    }
}

// ---------------- masked mean ----------------
__global__ void meanpool_kernel(const float* __restrict__ attn_out, const int* __restrict__ lengths,
                                float* __restrict__ pr) {
    int p = blockIdx.x, t = threadIdx.x;
    int len = lengths[p];
    const float* b = attn_out + (size_t)p * 32 * 512 + t;
    float acc = 0.0f;
    for (int l = 0; l < len; l++) acc += b[(size_t)l * 512];
    pr[(size_t)p * 512 + t] = acc / (float)len;
}

// ---------------- layernorm over D=768 ----------------
__global__ void ln_kernel(const float* __restrict__ x, const float* __restrict__ w,
                          const float* __restrict__ b, float* __restrict__ y) {
    __shared__ float red[8];
    int m = blockIdx.x, t = threadIdx.x;
    const float* xr = x + (size_t)m * D_;
    float v0 = xr[t], v1 = xr[t + 256], v2 = xr[t + 512];

    float s = v0 + v1 + v2;
    #pragma unroll
    for (int o = 16; o; o >>= 1) s += __shfl_xor_sync(0xffffffffu, s, o);
    if ((t & 31) == 0) red[t >> 5] = s;
    __syncthreads();
    if (t < 8) {
        float v = red[t];
        #pragma unroll
        for (int o = 4; o; o >>= 1) v += __shfl_xor_sync(0xffu, v, o);
        if (t == 0) red[0] = v;
    }
    __syncthreads();
    float mu = red[0] * (1.0f / D_);
    __syncthreads();

    float d0 = v0 - mu, d1 = v1 - mu, d2 = v2 - mu;
    float sq = d0 * d0 + d1 * d1 + d2 * d2;
    #pragma unroll
    for (int o = 16; o; o >>= 1) sq += __shfl_xor_sync(0xffffffffu, sq, o);
    if ((t & 31) == 0) red[t >> 5] = sq;
    __syncthreads();
    if (t < 8) {
        float v = red[t];
        #pragma unroll
        for (int o = 4; o; o >>= 1) v += __shfl_xor_sync(0xffu, v, o);
        if (t == 0) red[0] = v;
    }
    __syncthreads();
    float rstd = rsqrtf(red[0] * (1.0f / D_) + 1e-5f);

    float* yr = y + (size_t)m * D_;
    yr[t]       = d0 * rstd * w[t]       + b[t];
    yr[t + 256] = d1 * rstd * w[t + 256] + b[t + 256];
    yr[t + 512] = d2 * rstd * w[t + 512] + b[t + 512];
}

// ---------------- transformer attention: S=1024, d=96, 8 heads ----------------
__global__ void __launch_bounds__(128)
trans_attn_kernel(const float* __restrict__ qkv, float* __restrict__ ctx) {
    __shared__ float sQ[8][96];
    __shared__ float sKV[32][97];
    __shared__ float sS[8][1024];

    int qt = blockIdx.x, h = blockIdx.y, t = threadIdx.x;
    int q0 = qt * 8;
    const float scale = 0.10206207261596575f;

    for (int u = t; u < 8 * 96; u += 128) {
        int i = u / 96, dd = u - i * 96;
        sQ[i][dd] = qkv[(size_t)(q0 + i) * 2304 + h * 96 + dd] * scale;
    }
    __syncthreads();

    for (int kt = 0; kt < 32; kt++) {
        int j0 = kt * 32;
        for (int u = t; u < 32 * 96; u += 128) {
            int j = u / 96, dd = u - j * 96;
            sKV[j][dd] = qkv[(size_t)(j0 + j) * 2304 + 768 + h * 96 + dd];
        }
        __syncthreads();
        #pragma unroll
        for (int w = 0; w < 2; w++) {
            int idx = t + w * 128;
            int i = idx >> 5, j = idx & 31;
            float acc = 0.0f;
            #pragma unroll 8
            for (int kk = 0; kk < 96; kk++) acc = fmaf(sQ[i][kk], sKV[j][kk], acc);
            sS[i][j0 + j] = acc;
        }
        __syncthreads();
    }

    {
        int i = t >> 4, lane = t & 15;
        float mx = -1e30f;
        for (int j = lane; j < 1024; j += 16) mx = fmaxf(mx, sS[i][j]);
        #pragma unroll
        for (int o = 8; o; o >>= 1) mx = fmaxf(mx, __shfl_xor_sync(0xffffffffu, mx, o, 16));
        float sum = 0.0f;
        for (int j = lane; j < 1024; j += 16) { float e = __expf(sS[i][j] - mx); sS[i][j] = e; sum += e; }
        #pragma unroll
        for (int o = 8; o; o >>= 1) sum += __shfl_xor_sync(0xffffffffu, sum, o, 16);
        float inv = 1.0f / sum;
        for (int j = lane; j < 1024; j += 16) sS[i][j] *= inv;
    }
    __syncthreads();

    float acc[6] = {0, 0, 0, 0, 0, 0};
    int io[6], ddo[6];
    #pragma unroll
    for (int w = 0; w < 6; w++) { int o = t + w * 128; io[w] = o / 96; ddo[w] = o - io[w] * 96; }

    for (int vt = 0; vt < 32; vt++) {
        int j0 = vt * 32;
        for (int u = t; u < 32 * 96; u += 128) {
            int j = u / 96, dd = u - j * 96;
            sKV[j][dd] = qkv[(size_t)(j0 + j) * 2304 + 1536 + h * 96 + dd];
        }
        __syncthreads();
        #pragma unroll
        for (int w = 0; w < 6; w++) {
            float a = 0.0f;
            #pragma unroll
            for (int j = 0; j < 32; j++) a = fmaf(sS[io[w]][j0 + j], sKV[j][ddo[w]], a);
            acc[w] += a;
        }
        __syncthreads();
    }
    #pragma unroll
    for (int w = 0; w < 6; w++)
        ctx[(size_t)(q0 + io[w]) * 768 + h * 96 + ddo[w]] = acc[w];
}

// ---------------- host driver ----------------
static void run_gemm(const float* A, const float* W, const float* bias, const float* Res,
                     float* C, int M, int N, int K, int act,
                     __nv_bfloat16* ahi, __nv_bfloat16* alo,
                     __nv_bfloat16* whi, __nv_bfloat16* wlo) {
    int na4 = (M * K) / 4, nw4 = (N * K) / 4;
    split_kernel<<<(na4 + 255) / 256, 256>>>(A, ahi, alo, na4);
    split_kernel<<<(nw4 + 255) / 256, 256>>>(W, whi, wlo, nw4);
    dim3 grid(N / 128, M / 128), block(256);
    if (act) mma_gemm<1><<<grid, block, GSMEM>>>(ahi, alo, whi, wlo, bias, Res, C, M, N, K);
    else     mma_gemm<0><<<grid, block, GSMEM>>>(ahi, alo, whi, wlo, bias, Res, C, M, N, K);
}

extern "C" void kernel_launch(void* const* d_in, const int* in_sizes, int n_in,
                              void* d_out, int out_size) {
    const int*   tokens   = (const int*)d_in[0];
    const int*   lengths  = (const int*)d_in[1];
    const float* byte_emb = (const float*)d_in[2];
    const float* lpos     = (const float*)d_in[3];
    const float* ppos     = (const float*)d_in[4];
    const float* pa_qkv_w = (const float*)d_in[5];
    const float* pa_qkv_b = (const float*)d_in[6];
    const float* pa_out_w = (const float*)d_in[7];
    const float* pa_out_b = (const float*)d_in[8];
    const float* proj_w   = (const float*)d_in[9];
    const float* proj_b   = (const float*)d_in[10];
    const float* lqkv_w   = (const float*)d_in[11];
    const float* lqkv_b   = (const float*)d_in[12];
    const float* lout_w   = (const float*)d_in[13];
    const float* lout_b   = (const float*)d_in[14];
    const float* ln1w     = (const float*)d_in[15];
    const float* ln1b     = (const float*)d_in[16];
    const float* ln2w     = (const float*)d_in[17];
    const float* ln2b     = (const float*)d_in[18];
    const float* ff1w     = (const float*)d_in[19];
    const float* ff1b     = (const float*)d_in[20];
    const float* ff2w     = (const float*)d_in[21];
    const float* ff2b     = (const float*)d_in[22];
    const float* lnfw     = (const float*)d_in[23];
    const float* lnfb     = (const float*)d_in[24];
    float* out = (float*)d_out;

    cudaFuncSetAttribute(mma_gemm<0>, cudaFuncAttributeMaxDynamicSharedMemorySize, GSMEM);
    cudaFuncSetAttribute(mma_gemm<1>, cudaFuncAttributeMaxDynamicSharedMemorySize, GSMEM);

    float *emb, *qkvb, *ctxb, *pr, *h, *hn, *ffb;
    __nv_bfloat16 *ahi, *alo, *whi, *wlo;
    cudaGetSymbolAddress((void**)&emb,  g_emb);
    cudaGetSymbolAddress((void**)&qkvb, g_qkv);
    cudaGetSymbolAddress((void**)&ctxb, g_ctx);
    cudaGetSymbolAddress((void**)&pr,   g_pr);
    cudaGetSymbolAddress((void**)&h,    g_h);
    cudaGetSymbolAddress((void**)&hn,   g_hn);
    cudaGetSymbolAddress((void**)&ffb,  g_ff);
    cudaGetSymbolAddress((void**)&ahi,  g_ahi);
    cudaGetSymbolAddress((void**)&alo,  g_alo);
    cudaGetSymbolAddress((void**)&whi,  g_whi);
    cudaGetSymbolAddress((void**)&wlo,  g_wlo);

    // 1) embeddings (masked)
    embed_kernel<<<P_ * L_, 256>>>(tokens, lengths, byte_emb, lpos, emb);

    // 2) local qkv: [32768,512] @ [1536,512]^T
    run_gemm(emb, pa_qkv_w, pa_qkv_b, nullptr, qkvb, P_ * L_, 3 * E_, E_, 0, ahi, alo, whi, wlo);

    // 3) per-patch attention
    local_attn_kernel<<<dim3(P_, HPA_), 128>>>(qkvb, lengths, ctxb);

    // 4) local out-proj -> reuse emb as attn output
    run_gemm(ctxb, pa_out_w, pa_out_b, nullptr, emb, P_ * L_, E_, E_, 0, ahi, alo, whi, wlo);

    // 5) masked mean -> patch_repr
    meanpool_kernel<<<P_, 512>>>(emb, lengths, pr);

    // 6) project + patch positions -> h
    run_gemm(pr, proj_w, proj_b, ppos, h, P_, D_, E_, 0, ahi, alo, whi, wlo);

    // 7) transformer layers
    for (int i = 0; i < NL_; i++) {
        ln_kernel<<<P_, 256>>>(h, ln1w + (size_t)i * D_, ln1b + (size_t)i * D_, hn);
        run_gemm(hn, lqkv_w + (size_t)i * 3 * D_ * D_, lqkv_b + (size_t)i * 3 * D_,
                 nullptr, qkvb, P_, 3 * D_, D_, 0, ahi, alo, whi, wlo);
        trans_attn_kernel<<<dim3(128, HTR_), 128>>>(qkvb, ctxb);
        run_gemm(ctxb, lout_w + (size_t)i * D_ * D_, lout_b + (size_t)i * D_,
                 h, h, P_, D_, D_, 0, ahi, alo, whi, wlo);
        ln_kernel<<<P_, 256>>>(h, ln2w + (size_t)i * D_, ln2b + (size_t)i * D_, hn);
        run_gemm(hn, ff1w + (size_t)i * FF_ * D_, ff1b + (size_t)i * FF_,
                 nullptr, ffb, P_, FF_, D_, 1, ahi, alo, whi, wlo);
        run_gemm(ffb, ff2w + (size_t)i * D_ * FF_, ff2b + (size_t)i * D_,
                 h, h, P_, D_, FF_, 0, ahi, alo, whi, wlo);
    }

    // 8) final layernorm -> output
    ln_kernel<<<P_, 256>>>(h, lnfw, lnfb, out);
}